// round 6
// baseline (speedup 1.0000x reference)
#include <cuda_runtime.h>
#include <cstdint>
#include <math.h>

#define BETA   5.5f
#define NC     1000
#define NM     50
#define NR     51        // rows incl. vanilla
#define ND     1024
#define ND4    256
#define QB     125
#define QROWS  8
#define NW     8         // warps per CTA

__device__ __align__(16) float g_qn[ND];
__device__ float g_logits[NC];
__device__ float g_qpart[QB * ND];
__device__ unsigned int g_ctr_q = 0;
__device__ unsigned int g_ctr_m = 0;

__device__ __forceinline__ float dot4(const float4 a, const float4 b)
{
    return a.x * b.x + a.y * b.y + a.z * b.z + a.w * b.w;
}

// ---------------------------------------------------------------------------
// Kernel 1: qn = l2norm(img + mean(global_bias,0)). grid=125 x 1024, ticketed.
// ---------------------------------------------------------------------------
__global__ void qn_kernel(const float* __restrict__ gb,
                          const float* __restrict__ img)
{
    const int d = threadIdx.x;
    const int b = blockIdx.x;
    const float* base = gb + (size_t)b * QROWS * ND + d;
    float s = 0.0f;
    #pragma unroll
    for (int r = 0; r < QROWS; ++r) s += base[r * ND];
    g_qpart[b * ND + d] = s;

    __shared__ unsigned int ticket;
    __threadfence();
    __syncthreads();
    if (d == 0) ticket = atomicAdd(&g_ctr_q, 1u);
    __syncthreads();
    if (ticket != QB - 1) return;

    float tsum = 0.0f;
    #pragma unroll 5
    for (int bb = 0; bb < QB; ++bb) tsum += g_qpart[bb * ND + d];
    const float q = img[d] + tsum * (1.0f / (float)NC);

    __shared__ float red[32];
    float v = q * q;
    #pragma unroll
    for (int o = 16; o; o >>= 1) v += __shfl_xor_sync(0xffffffffu, v, o);
    const int w = d >> 5, lane = d & 31;
    if (lane == 0) red[w] = v;
    __syncthreads();
    float tot = 0.0f;
    #pragma unroll
    for (int i = 0; i < 32; ++i) tot += red[i];

    g_qn[d] = q * rsqrtf(tot);
    if (d == 0) g_ctr_q = 0;
}

// ---------------------------------------------------------------------------
// per-row work: 4 joint dots + warp reduce + weight + acc update
// ---------------------------------------------------------------------------
__device__ __forceinline__ void process_row(const float4* __restrict__ x,
                                            float4* __restrict__ acc,
                                            float& sw,
                                            const float4* __restrict__ qn_s,
                                            const float4* __restrict__ bk_s,
                                            const float4* __restrict__ bv_s,
                                            float qk_c, float kk_c, float vv_c,
                                            int lane)
{
    float xx = 0.f, qx = 0.f, xk = 0.f, xv = 0.f;
    #pragma unroll
    for (int j = 0; j < 8; ++j) {
        const int idx = j * 32 + lane;
        const float4 q = qn_s[idx];
        const float4 k = bk_s[idx];
        const float4 v = bv_s[idx];
        xx += dot4(x[j], x[j]);
        qx += dot4(q, x[j]);
        xk += dot4(k, x[j]);
        xv += dot4(v, x[j]);
    }
    #pragma unroll
    for (int o = 16; o; o >>= 1) {
        xx += __shfl_xor_sync(0xffffffffu, xx, o);
        qx += __shfl_xor_sync(0xffffffffu, qx, o);
        xk += __shfl_xor_sync(0xffffffffu, xk, o);
        xv += __shfl_xor_sync(0xffffffffu, xv, o);
    }
    float w = 0.0f;
    if (xx != 0.0f) {                      // all-zero row <=> |x|^2 == 0
        const float dq = qx + qk_c;
        const float k2 = xx + 2.0f * xk + kk_c;
        const float v2 = xx + 2.0f * xv + vv_c;
        w = __expf(-BETA * (1.0f - dq * rsqrtf(k2))) * rsqrtf(v2);
    }
    sw += w;
    #pragma unroll
    for (int j = 0; j < 8; ++j) {
        acc[j].x += w * x[j].x;
        acc[j].y += w * x[j].y;
        acc[j].z += w * x[j].z;
        acc[j].w += w * x[j].w;
    }
}

__device__ __forceinline__ void load_row(float4* __restrict__ dst,
                                         const float4* __restrict__ mem4,
                                         const float4* __restrict__ van4,
                                         int m, int lane)
{
    const float4* r = (m < NM) ? (mem4 + (size_t)m * ND4) : van4;
    #pragma unroll
    for (int j = 0; j < 8; ++j) dst[j] = r[j * 32 + lane];
}

// ---------------------------------------------------------------------------
// Kernel 2: per-class attention. grid=1000, block=256 (8 warps).
// Warp wi handles rows m = wi, wi+8, ... (row 50 = vanilla).
// Register double buffer (1 row ahead), no mainloop barriers.
// Last CTA runs the softmax.
// ---------------------------------------------------------------------------
__global__ void __launch_bounds__(256, 2)
dualmem_main_kernel(const float* __restrict__ mem,
                    const float* __restrict__ van,
                    const float* __restrict__ gbk,
                    const float* __restrict__ gbv,
                    const float* __restrict__ ffn,
                    const float* __restrict__ img,
                    const float* __restrict__ scale,
                    float* __restrict__ out)
{
    __shared__ float4 qn_s[ND4];
    __shared__ float4 bk_s[ND4];
    __shared__ float4 bv_s[ND4];
    __shared__ float4 accs[NW][ND4];      // 32 KB combine scratch
    __shared__ float  sw_s[NW];
    __shared__ float4 redc[NW];
    __shared__ float  red1[NW];
    __shared__ float2 red2[NW];
    __shared__ float  redm[NW], reds[NW];
    __shared__ unsigned int ticket;

    const int c    = blockIdx.x;
    const int t    = threadIdx.x;       // 0..255
    const int wi   = t >> 5;            // 0..7
    const int lane = t & 31;

    const float4* qn4  = (const float4*)g_qn;
    const float4* gbk4 = (const float4*)(gbk + (size_t)c * ND);
    const float4* gbv4 = (const float4*)(gbv + (size_t)c * ND);
    const float4* mem4 = (const float4*)(mem + (size_t)c * NM * ND);
    const float4* van4 = (const float4*)(van + (size_t)c * ND);

    // kick off the first row load immediately (wi < NM always)
    float4 A[8], B[8];
    load_row(A, mem4, van4, wi, lane);

    // stage qn/bk/bv (one float4 per thread) + per-class constants
    {
        const float4 q = qn4[t];
        const float4 k = gbk4[t];
        const float4 v = gbv4[t];
        qn_s[t] = q; bk_s[t] = k; bv_s[t] = v;
        float pqk = dot4(q, k);
        float pkk = dot4(k, k);
        float pvv = dot4(v, v);
        #pragma unroll
        for (int o = 16; o; o >>= 1) {
            pqk += __shfl_xor_sync(0xffffffffu, pqk, o);
            pkk += __shfl_xor_sync(0xffffffffu, pkk, o);
            pvv += __shfl_xor_sync(0xffffffffu, pvv, o);
        }
        if (lane == 0) redc[wi] = make_float4(pqk, pkk, pvv, 0.0f);
    }
    __syncthreads();
    float qk_c = 0.0f, kk_c = 0.0f, vv_c = 0.0f;
    #pragma unroll
    for (int i = 0; i < NW; ++i) {
        qk_c += redc[i].x; kk_c += redc[i].y; vv_c += redc[i].z;
    }

    // --- mainloop: double-buffered rows, stride NW, no block barriers ---
    float4 acc[8];
    #pragma unroll
    for (int j = 0; j < 8; ++j) acc[j] = make_float4(0.f, 0.f, 0.f, 0.f);
    float sw = 0.0f;

    int m = wi;
    while (true) {
        int mn = m + NW;
        if (mn < NR) load_row(B, mem4, van4, mn, lane);
        process_row(A, acc, sw, qn_s, bk_s, bv_s, qk_c, kk_c, vv_c, lane);
        if (mn >= NR) break;
        m = mn;

        mn = m + NW;
        if (mn < NR) load_row(A, mem4, van4, mn, lane);
        process_row(B, acc, sw, qn_s, bk_s, bv_s, qk_c, kk_c, vv_c, lane);
        if (mn >= NR) break;
        m = mn;
    }

    // --- combine warps ---
    #pragma unroll
    for (int j = 0; j < 8; ++j) accs[wi][j * 32 + lane] = acc[j];
    if (lane == 0) sw_s[wi] = sw;
    __syncthreads();

    float swt = 0.0f;
    #pragma unroll
    for (int i = 0; i < NW; ++i) swt += sw_s[i];

    float4 s = accs[0][t];
    #pragma unroll
    for (int w = 1; w < NW; ++w) {
        const float4 p = accs[w][t];
        s.x += p.x; s.y += p.y; s.z += p.z; s.w += p.w;
    }
    const float4 b0 = bv_s[t];
    s.x += swt * b0.x; s.y += swt * b0.y; s.z += swt * b0.z; s.w += swt * b0.w;

    // l2norm(acc)
    float n1 = dot4(s, s);
    #pragma unroll
    for (int o = 16; o; o >>= 1) n1 += __shfl_xor_sync(0xffffffffu, n1, o);
    if (lane == 0) red1[wi] = n1;
    __syncthreads();
    float n1t = 0.0f;
    #pragma unroll
    for (int i = 0; i < NW; ++i) n1t += red1[i];
    const float rin1 = rsqrtf(n1t);

    // + ffn, l2norm, dot img
    const float4 f0 = ((const float4*)(ffn + (size_t)c * ND))[t];
    const float4 i0 = ((const float4*)img)[t];
    const float4 af = make_float4(s.x * rin1 + f0.x, s.y * rin1 + f0.y,
                                  s.z * rin1 + f0.z, s.w * rin1 + f0.w);

    float n2 = dot4(af, af);
    float dp = dot4(af, i0);
    #pragma unroll
    for (int o = 16; o; o >>= 1) {
        n2 += __shfl_xor_sync(0xffffffffu, n2, o);
        dp += __shfl_xor_sync(0xffffffffu, dp, o);
    }
    if (lane == 0) red2[wi] = make_float2(n2, dp);
    __syncthreads();

    if (t == 0) {
        float n2t = 0.0f, dpt = 0.0f;
        #pragma unroll
        for (int i = 0; i < NW; ++i) { n2t += red2[i].x; dpt += red2[i].y; }
        g_logits[c] = expf(scale[0]) * dpt * rsqrtf(n2t);
    }

    // --- last CTA: softmax over g_logits ---
    __threadfence();
    __syncthreads();
    if (t == 0) ticket = atomicAdd(&g_ctr_m, 1u);
    __syncthreads();
    if (ticket != NC - 1) return;

    float x[4];
    #pragma unroll
    for (int k = 0; k < 4; ++k) {
        const int i = t + k * 256;
        x[k] = (i < NC) ? g_logits[i] : -INFINITY;
    }
    float mx = fmaxf(fmaxf(x[0], x[1]), fmaxf(x[2], x[3]));
    #pragma unroll
    for (int o = 16; o; o >>= 1) mx = fmaxf(mx, __shfl_xor_sync(0xffffffffu, mx, o));
    if (lane == 0) redm[wi] = mx;
    __syncthreads();
    mx = redm[0];
    #pragma unroll
    for (int i = 1; i < NW; ++i) mx = fmaxf(mx, redm[i]);

    float e[4];
    float es = 0.0f;
    #pragma unroll
    for (int k = 0; k < 4; ++k) {
        const int i = t + k * 256;
        e[k] = (i < NC) ? expf(x[k] - mx) : 0.0f;
        es += e[k];
    }
    #pragma unroll
    for (int o = 16; o; o >>= 1) es += __shfl_xor_sync(0xffffffffu, es, o);
    if (lane == 0) reds[wi] = es;
    __syncthreads();
    float stot = 0.0f;
    #pragma unroll
    for (int i = 0; i < NW; ++i) stot += reds[i];
    const float rst = 1.0f / stot;

    #pragma unroll
    for (int k = 0; k < 4; ++k) {
        const int i = t + k * 256;
        if (i < NC) out[i] = e[k] * rst;
    }
    if (t == 0) g_ctr_m = 0;
}

// ---------------------------------------------------------------------------
extern "C" void kernel_launch(void* const* d_in, const int* in_sizes, int n_in,
                              void* d_out, int out_size)
{
    const float* img   = (const float*)d_in[0];
    const float* mem   = (const float*)d_in[1];
    const float* van   = (const float*)d_in[2];
    const float* gb    = (const float*)d_in[3];
    const float* gbk   = (const float*)d_in[4];
    const float* gbv   = (const float*)d_in[5];
    const float* ffn   = (const float*)d_in[6];
    const float* scale = (const float*)d_in[7];

    qn_kernel<<<QB, 1024>>>(gb, img);
    dualmem_main_kernel<<<NC, 256>>>(mem, van, gbk, gbv, ffn, img, scale,
                                     (float*)d_out);
}

// round 7
// speedup vs baseline: 1.4441x; 1.4441x over previous
#include <cuda_runtime.h>
#include <cstdint>
#include <math.h>

#define BETA   5.5f
#define NC     1000
#define NM     50
#define NR     51        // rows incl. vanilla
#define ND     1024
#define ND4    256
#define QB     125
#define QROWS  8

typedef unsigned long long u64;

__device__ __align__(16) float g_qn[ND];
__device__ float g_logits[NC];
__device__ float g_qpart[QB * ND];
__device__ unsigned int g_ctr_q = 0;
__device__ unsigned int g_ctr_m = 0;

__device__ __forceinline__ u64 fma2(u64 a, u64 b, u64 c)
{
    u64 d;
    asm("fma.rn.f32x2 %0, %1, %2, %3;" : "=l"(d) : "l"(a), "l"(b), "l"(c));
    return d;
}
__device__ __forceinline__ float2 unpack2(u64 v)
{
    float2 f;
    asm("mov.b64 {%0, %1}, %2;" : "=f"(f.x), "=f"(f.y) : "l"(v));
    return f;
}
__device__ __forceinline__ u64 pack2(float lo, float hi)
{
    u64 v;
    asm("mov.b64 %0, {%1, %2};" : "=l"(v) : "f"(lo), "f"(hi));
    return v;
}
__device__ __forceinline__ float dot4(const float4 a, const float4 b)
{
    return a.x * b.x + a.y * b.y + a.z * b.z + a.w * b.w;
}

// ---------------------------------------------------------------------------
// Kernel 1: qn = l2norm(img + mean(global_bias,0)). grid=125 x 1024, ticketed.
// ---------------------------------------------------------------------------
__global__ void qn_kernel(const float* __restrict__ gb,
                          const float* __restrict__ img)
{
    const int d = threadIdx.x;
    const int b = blockIdx.x;
    const float* base = gb + (size_t)b * QROWS * ND + d;
    float s = 0.0f;
    #pragma unroll
    for (int r = 0; r < QROWS; ++r) s += base[r * ND];
    g_qpart[b * ND + d] = s;

    __shared__ unsigned int ticket;
    __threadfence();
    __syncthreads();
    if (d == 0) ticket = atomicAdd(&g_ctr_q, 1u);
    __syncthreads();
    if (ticket != QB - 1) return;

    float tsum = 0.0f;
    #pragma unroll 5
    for (int bb = 0; bb < QB; ++bb) tsum += g_qpart[bb * ND + d];
    const float q = img[d] + tsum * (1.0f / (float)NC);

    __shared__ float red[32];
    float v = q * q;
    #pragma unroll
    for (int o = 16; o; o >>= 1) v += __shfl_xor_sync(0xffffffffu, v, o);
    const int w = d >> 5, lane = d & 31;
    if (lane == 0) red[w] = v;
    __syncthreads();
    float tot = 0.0f;
    #pragma unroll
    for (int i = 0; i < 32; ++i) tot += red[i];

    g_qn[d] = q * rsqrtf(tot);
    if (d == 0) g_ctr_q = 0;
}

// ---------------------------------------------------------------------------
// Kernel 2: per-class attention, warp-per-row, packed f32x2 math.
// grid=1000, block=128 (4 warps). Warp wi: rows wi, wi+4, ... (50 = vanilla).
// Register double buffer (1 row ahead), no mainloop barriers.
// Last CTA runs the softmax.
// ---------------------------------------------------------------------------
__global__ void __launch_bounds__(128, 3)
dualmem_main_kernel(const float* __restrict__ mem,
                    const float* __restrict__ van,
                    const float* __restrict__ gbk,
                    const float* __restrict__ gbv,
                    const float* __restrict__ ffn,
                    const float* __restrict__ img,
                    const float* __restrict__ scale,
                    float* __restrict__ out)
{
    __shared__ ulonglong2 qn_s[ND4];
    __shared__ ulonglong2 bk_s[ND4];
    __shared__ ulonglong2 bv_s[ND4];
    __shared__ float4 accs[4][ND4];      // 16 KB combine scratch
    __shared__ float  sw_s[4];
    __shared__ float4 redc[4];
    __shared__ float  red1[4];
    __shared__ float2 red2[4];
    __shared__ float  redm[4], reds[4];
    __shared__ unsigned int ticket;

    const int c    = blockIdx.x;
    const int t    = threadIdx.x;       // 0..127
    const int wi   = t >> 5;
    const int lane = t & 31;

    const float4* qn4  = (const float4*)g_qn;
    const float4* gbk4 = (const float4*)(gbk + (size_t)c * ND);
    const float4* gbv4 = (const float4*)(gbv + (size_t)c * ND);
    const ulonglong2* mem2 = (const ulonglong2*)(mem + (size_t)c * NM * ND);
    const ulonglong2* van2 = (const ulonglong2*)(van + (size_t)c * ND);

    // first row load straight away (wi < NM always)
    ulonglong2 xr[8], xn[8];
    {
        const ulonglong2* rp = mem2 + (size_t)wi * ND4;
        #pragma unroll
        for (int j = 0; j < 8; ++j) xr[j] = rp[j * 32 + lane];
    }

    // stage qn/bk/bv + per-class constants (2 float4 per thread)
    float pqk = 0.0f, pkk = 0.0f, pvv = 0.0f;
    #pragma unroll
    for (int r = 0; r < 2; ++r) {
        const int idx = t + r * 128;
        const float4 q = qn4[idx];
        const float4 k = gbk4[idx];
        const float4 v = gbv4[idx];
        *(float4*)&qn_s[idx] = q;
        *(float4*)&bk_s[idx] = k;
        *(float4*)&bv_s[idx] = v;
        pqk += dot4(q, k);
        pkk += dot4(k, k);
        pvv += dot4(v, v);
    }
    #pragma unroll
    for (int o = 16; o; o >>= 1) {
        pqk += __shfl_xor_sync(0xffffffffu, pqk, o);
        pkk += __shfl_xor_sync(0xffffffffu, pkk, o);
        pvv += __shfl_xor_sync(0xffffffffu, pvv, o);
    }
    if (lane == 0) redc[wi] = make_float4(pqk, pkk, pvv, 0.0f);
    __syncthreads();
    float qk_c = 0.0f, kk_c = 0.0f, vv_c = 0.0f;
    #pragma unroll
    for (int i = 0; i < 4; ++i) {
        qk_c += redc[i].x; kk_c += redc[i].y; vv_c += redc[i].z;
    }

    // --- mainloop: packed-f32x2, double-buffered, no block barriers ---
    u64 acc[16];
    #pragma unroll
    for (int j = 0; j < 16; ++j) acc[j] = 0ull;
    float sw = 0.0f;

    int m = wi;
    while (true) {
        const int  mn = m + 4;
        const bool hn = (mn <= NM);
        if (hn) {
            const ulonglong2* rq = (mn < NM) ? (mem2 + (size_t)mn * ND4) : van2;
            #pragma unroll
            for (int j = 0; j < 8; ++j) xn[j] = rq[j * 32 + lane];
        }

        u64 xx_p = 0ull, qx_p = 0ull, xk_p = 0ull, xv_p = 0ull;
        #pragma unroll
        for (int j = 0; j < 8; ++j) {
            const int idx = j * 32 + lane;
            const ulonglong2 q = qn_s[idx];
            const ulonglong2 k = bk_s[idx];
            const ulonglong2 v = bv_s[idx];
            const ulonglong2 x = xr[j];
            xx_p = fma2(x.x, x.x, xx_p); xx_p = fma2(x.y, x.y, xx_p);
            qx_p = fma2(q.x, x.x, qx_p); qx_p = fma2(q.y, x.y, qx_p);
            xk_p = fma2(k.x, x.x, xk_p); xk_p = fma2(k.y, x.y, xk_p);
            xv_p = fma2(v.x, x.x, xv_p); xv_p = fma2(v.y, x.y, xv_p);
        }
        const float2 xx2 = unpack2(xx_p);
        const float2 qx2 = unpack2(qx_p);
        const float2 xk2 = unpack2(xk_p);
        const float2 xv2 = unpack2(xv_p);
        float xx = xx2.x + xx2.y;
        float qx = qx2.x + qx2.y;
        float xk = xk2.x + xk2.y;
        float xv = xv2.x + xv2.y;
        #pragma unroll
        for (int o = 16; o; o >>= 1) {
            xx += __shfl_xor_sync(0xffffffffu, xx, o);
            qx += __shfl_xor_sync(0xffffffffu, qx, o);
            xk += __shfl_xor_sync(0xffffffffu, xk, o);
            xv += __shfl_xor_sync(0xffffffffu, xv, o);
        }

        float w = 0.0f;
        if (xx != 0.0f) {                  // all-zero row <=> |x|^2 == 0
            const float dq = qx + qk_c;
            const float k2 = xx + 2.0f * xk + kk_c;
            const float v2 = xx + 2.0f * xv + vv_c;
            w = __expf(-BETA * (1.0f - dq * rsqrtf(k2))) * rsqrtf(v2);
        }
        sw += w;
        const u64 w2 = pack2(w, w);
        #pragma unroll
        for (int j = 0; j < 8; ++j) {
            acc[2 * j + 0] = fma2(w2, xr[j].x, acc[2 * j + 0]);
            acc[2 * j + 1] = fma2(w2, xr[j].y, acc[2 * j + 1]);
        }

        if (!hn) break;
        #pragma unroll
        for (int j = 0; j < 8; ++j) xr[j] = xn[j];
        m = mn;
    }

    // --- combine warps: acc_total = sum_w acc + sw_total * bv ---
    #pragma unroll
    for (int j = 0; j < 8; ++j) {
        const float2 lo = unpack2(acc[2 * j + 0]);
        const float2 hi = unpack2(acc[2 * j + 1]);
        accs[wi][j * 32 + lane] = make_float4(lo.x, lo.y, hi.x, hi.y);
    }
    if (lane == 0) sw_s[wi] = sw;
    __syncthreads();

    const float swt = sw_s[0] + sw_s[1] + sw_s[2] + sw_s[3];
    float4 a0, a1;
    {
        const int i0 = t, i1 = t + 128;
        float4 s0 = accs[0][i0], s1 = accs[0][i1];
        #pragma unroll
        for (int w = 1; w < 4; ++w) {
            const float4 p = accs[w][i0], q = accs[w][i1];
            s0.x += p.x; s0.y += p.y; s0.z += p.z; s0.w += p.w;
            s1.x += q.x; s1.y += q.y; s1.z += q.z; s1.w += q.w;
        }
        const float4 b0 = *(const float4*)&bv_s[i0];
        const float4 b1 = *(const float4*)&bv_s[i1];
        a0 = make_float4(s0.x + swt*b0.x, s0.y + swt*b0.y, s0.z + swt*b0.z, s0.w + swt*b0.w);
        a1 = make_float4(s1.x + swt*b1.x, s1.y + swt*b1.y, s1.z + swt*b1.z, s1.w + swt*b1.w);
    }

    float n1 = dot4(a0, a0) + dot4(a1, a1);
    #pragma unroll
    for (int o = 16; o; o >>= 1) n1 += __shfl_xor_sync(0xffffffffu, n1, o);
    if (lane == 0) red1[wi] = n1;
    __syncthreads();
    const float rin1 = rsqrtf(red1[0] + red1[1] + red1[2] + red1[3]);

    const float4* ffn4 = (const float4*)(ffn + (size_t)c * ND);
    const float4* img4 = (const float4*)img;
    const float4 f0 = ffn4[t], f1 = ffn4[t + 128];
    const float4 i0 = img4[t], i1 = img4[t + 128];
    const float4 af0 = make_float4(a0.x*rin1 + f0.x, a0.y*rin1 + f0.y,
                                   a0.z*rin1 + f0.z, a0.w*rin1 + f0.w);
    const float4 af1 = make_float4(a1.x*rin1 + f1.x, a1.y*rin1 + f1.y,
                                   a1.z*rin1 + f1.z, a1.w*rin1 + f1.w);

    float n2 = dot4(af0, af0) + dot4(af1, af1);
    float dp = dot4(af0, i0) + dot4(af1, i1);
    #pragma unroll
    for (int o = 16; o; o >>= 1) {
        n2 += __shfl_xor_sync(0xffffffffu, n2, o);
        dp += __shfl_xor_sync(0xffffffffu, dp, o);
    }
    if (lane == 0) red2[wi] = make_float2(n2, dp);
    __syncthreads();

    if (t == 0) {
        float n2t = 0.0f, dpt = 0.0f;
        #pragma unroll
        for (int i = 0; i < 4; ++i) { n2t += red2[i].x; dpt += red2[i].y; }
        g_logits[c] = expf(scale[0]) * dpt * rsqrtf(n2t);
    }

    // --- last CTA: softmax over g_logits ---
    __threadfence();
    __syncthreads();
    if (t == 0) ticket = atomicAdd(&g_ctr_m, 1u);
    __syncthreads();
    if (ticket != NC - 1) return;

    float x[8];
    #pragma unroll
    for (int k = 0; k < 8; ++k) {
        const int i = t + k * 128;
        x[k] = (i < NC) ? g_logits[i] : -INFINITY;
    }
    float mx = x[0];
    #pragma unroll
    for (int k = 1; k < 8; ++k) mx = fmaxf(mx, x[k]);
    #pragma unroll
    for (int o = 16; o; o >>= 1) mx = fmaxf(mx, __shfl_xor_sync(0xffffffffu, mx, o));
    if (lane == 0) redm[wi] = mx;
    __syncthreads();
    mx = fmaxf(fmaxf(redm[0], redm[1]), fmaxf(redm[2], redm[3]));

    float e[8];
    float es = 0.0f;
    #pragma unroll
    for (int k = 0; k < 8; ++k) {
        const int i = t + k * 128;
        e[k] = (i < NC) ? expf(x[k] - mx) : 0.0f;
        es += e[k];
    }
    #pragma unroll
    for (int o = 16; o; o >>= 1) es += __shfl_xor_sync(0xffffffffu, es, o);
    if (lane == 0) reds[wi] = es;
    __syncthreads();
    const float rst = 1.0f / (reds[0] + reds[1] + reds[2] + reds[3]);

    #pragma unroll
    for (int k = 0; k < 8; ++k) {
        const int i = t + k * 128;
        if (i < NC) out[i] = e[k] * rst;
    }
    if (t == 0) g_ctr_m = 0;
}

// ---------------------------------------------------------------------------
extern "C" void kernel_launch(void* const* d_in, const int* in_sizes, int n_in,
                              void* d_out, int out_size)
{
    const float* img   = (const float*)d_in[0];
    const float* mem   = (const float*)d_in[1];
    const float* van   = (const float*)d_in[2];
    const float* gb    = (const float*)d_in[3];
    const float* gbk   = (const float*)d_in[4];
    const float* gbv   = (const float*)d_in[5];
    const float* ffn   = (const float*)d_in[6];
    const float* scale = (const float*)d_in[7];

    qn_kernel<<<QB, 1024>>>(gb, img);
    dualmem_main_kernel<<<NC, 128>>>(mem, van, gbk, gbv, ffn, img, scale,
                                     (float*)d_out);
}